// round 1
// baseline (speedup 1.0000x reference)
#include <cuda_runtime.h>
#include <math.h>

#define TT   12
#define NN   50000
#define HH   128
#define OUTD 12

// ---------------- scratch (no allocations allowed) ----------------
// layout (floats):
//  h0[2] : 2*NH      c0 : NH      h1[2] : 2*NH     c1 : NH
//  hW : NH           agg : NH     dinv : 65536(pad)
//  Whh0T : 128*512   Wcat1T : 256*512   bias0 : 512  bias1 : 512
#define NH (NN * HH)                       // 6,400,000
__device__ float g_scratch[8 * NH + 65536 + 65536 + 131072 + 1024 + 1024];

__device__ __forceinline__ float sigf(float x) { return 1.0f / (1.0f + expf(-x)); }

// ---------------- utility kernels ----------------
__global__ void zero_k(float* p, int n) {
    int i = blockIdx.x * blockDim.x + threadIdx.x;
    if (i < n) p[i] = 0.0f;
}

__global__ void prep_weights(const float* __restrict__ Whh0,
                             const float* __restrict__ Wih1,
                             const float* __restrict__ Whh1,
                             const float* __restrict__ bih0, const float* __restrict__ bhh0,
                             const float* __restrict__ bih1, const float* __restrict__ bhh1,
                             float* __restrict__ whh0T, float* __restrict__ wcat1T,
                             float* __restrict__ bias0, float* __restrict__ bias1) {
    int idx = blockIdx.x * blockDim.x + threadIdx.x;   // 512*128 = 65536
    if (idx >= 512 * 128) return;
    int j = idx >> 7;        // 0..511  (gate-major output index)
    int k = idx & 127;       // 0..127
    whh0T[k * 512 + j]          = Whh0[j * 128 + k];
    wcat1T[k * 512 + j]         = Wih1[j * 128 + k];
    wcat1T[(128 + k) * 512 + j] = Whh1[j * 128 + k];
    if (k == 0) {
        bias0[j] = bih0[j] + bhh0[j];
        bias1[j] = bih1[j] + bhh1[j];
    }
}

__global__ void deg_init(float* deg) {
    int i = blockIdx.x * blockDim.x + threadIdx.x;
    if (i < NN) deg[i] = 1.0f;            // self-loop
}
__global__ void deg_count(const int* __restrict__ dst, float* deg, int E) {
    int i = blockIdx.x * blockDim.x + threadIdx.x;
    if (i < E) atomicAdd(&deg[dst[i]], 1.0f);
}
__global__ void deg_rsqrt(float* deg) {
    int i = blockIdx.x * blockDim.x + threadIdx.x;
    if (i < NN) deg[i] = rsqrtf(deg[i]);
}

// ---------------- fused LSTM step: z = A@Bt (+x-term) -> gates -> c,h ----------------
// Block tile: 128 nodes x 32 within-gate cols x 4 gates.  256 threads (16x16),
// per-thread micro-tile 8 nodes x 2 cols x 4 gates = 64 accumulators.
template<int KTOT, bool HASX>
__global__ __launch_bounds__(256)
void lstm_step(const float* __restrict__ A0, const float* __restrict__ A1,
               const float* __restrict__ Bt, const float* __restrict__ bias,
               const float* __restrict__ x, const float* __restrict__ Wih,
               int t, float* __restrict__ c, float* __restrict__ hout) {
    __shared__ float As[16][132];
    __shared__ float Bs[16][4][32];

    int tid = threadIdx.x;
    int ty = tid >> 4;           // 0..15 : node group
    int tx = tid & 15;           // 0..15 : col group
    int j0 = blockIdx.y * 32;    // within-gate col base
    int nbase = blockIdx.x * 128;

    float acc[8][4][2];
#pragma unroll
    for (int i = 0; i < 8; i++)
#pragma unroll
        for (int g = 0; g < 4; g++) { acc[i][g][0] = 0.f; acc[i][g][1] = 0.f; }

    int a_row = tid >> 2;            // 0..63
    int a_k4  = (tid & 3) * 4;       // 0,4,8,12
    int lane = tid & 31;
    int wseg = tid >> 5;             // 0..7

    for (int kc = 0; kc < KTOT; kc += 16) {
        const float* Asrc = A0;
        int koff = kc;
        if (KTOT == 256 && kc >= 128) { Asrc = A1; koff = kc - 128; }
        // A tile: 128 rows x 16 k, stored transposed
#pragma unroll
        for (int hh = 0; hh < 2; hh++) {
            int r = a_row + hh * 64;
            int n = nbase + r;
            float4 v = make_float4(0.f, 0.f, 0.f, 0.f);
            if (n < NN) v = *(const float4*)(Asrc + n * 128 + koff + a_k4);
            As[a_k4 + 0][r] = v.x; As[a_k4 + 1][r] = v.y;
            As[a_k4 + 2][r] = v.z; As[a_k4 + 3][r] = v.w;
        }
        // B tile: 16 k x 4 gates x 32 cols
#pragma unroll
        for (int it = 0; it < 8; it++) {
            int seg = it * 8 + wseg;     // 0..63
            int k = seg >> 2, g = seg & 3;
            Bs[k][g][lane] = Bt[(kc + k) * 512 + g * 128 + j0 + lane];
        }
        __syncthreads();
#pragma unroll
        for (int k = 0; k < 16; k++) {
            float a[8], b[4][2];
#pragma unroll
            for (int i = 0; i < 8; i++) a[i] = As[k][ty * 8 + i];
#pragma unroll
            for (int g = 0; g < 4; g++) { b[g][0] = Bs[k][g][tx * 2]; b[g][1] = Bs[k][g][tx * 2 + 1]; }
#pragma unroll
            for (int i = 0; i < 8; i++)
#pragma unroll
                for (int g = 0; g < 4; g++) {
                    acc[i][g][0] = fmaf(a[i], b[g][0], acc[i][g][0]);
                    acc[i][g][1] = fmaf(a[i], b[g][1], acc[i][g][1]);
                }
        }
        __syncthreads();
    }

    // epilogue: bias, optional x-term (IN=2), gates, cell update
    float bb[4][2];
    float wx[4][2][2];
#pragma unroll
    for (int g = 0; g < 4; g++)
#pragma unroll
        for (int jt = 0; jt < 2; jt++) {
            int j = j0 + tx * 2 + jt;
            bb[g][jt] = bias[g * 128 + j];
            if (HASX) {
                wx[g][jt][0] = Wih[(g * 128 + j) * 2 + 0];
                wx[g][jt][1] = Wih[(g * 128 + j) * 2 + 1];
            }
        }
#pragma unroll
    for (int i = 0; i < 8; i++) {
        int n = nbase + ty * 8 + i;
        if (n >= NN) continue;
        float x0 = 0.f, x1 = 0.f;
        if (HASX) { x0 = x[(n * TT + t) * 2 + 0]; x1 = x[(n * TT + t) * 2 + 1]; }
#pragma unroll
        for (int jt = 0; jt < 2; jt++) {
            int j = j0 + tx * 2 + jt;
            float zi = acc[i][0][jt] + bb[0][jt];
            float zf = acc[i][1][jt] + bb[1][jt];
            float zg = acc[i][2][jt] + bb[2][jt];
            float zo = acc[i][3][jt] + bb[3][jt];
            if (HASX) {
                zi += x0 * wx[0][jt][0] + x1 * wx[0][jt][1];
                zf += x0 * wx[1][jt][0] + x1 * wx[1][jt][1];
                zg += x0 * wx[2][jt][0] + x1 * wx[2][jt][1];
                zo += x0 * wx[3][jt][0] + x1 * wx[3][jt][1];
            }
            float cv = sigf(zf) * c[n * 128 + j] + sigf(zi) * tanhf(zg);
            c[n * 128 + j] = cv;
            hout[n * 128 + j] = sigf(zo) * tanhf(cv);
        }
    }
}

// ---------------- GCN GEMM: out[N,128] = (relu?)A[N,128] @ W[128,128] ----------------
__global__ __launch_bounds__(256)
void gcn_gemm(const float* __restrict__ A, const float* __restrict__ W,
              float* __restrict__ out, int relu) {
    __shared__ float As[16][68];
    __shared__ float Bs[16][128];
    int tid = threadIdx.x;
    int ty = tid >> 4, tx = tid & 15;
    int nbase = blockIdx.x * 64;
    float acc[4][8];
#pragma unroll
    for (int i = 0; i < 4; i++)
#pragma unroll
        for (int j = 0; j < 8; j++) acc[i][j] = 0.f;

    int a_row = tid >> 2;
    int a_k4  = (tid & 3) * 4;

    for (int kc = 0; kc < 128; kc += 16) {
        int n = nbase + a_row;
        float4 v = make_float4(0.f, 0.f, 0.f, 0.f);
        if (n < NN) v = *(const float4*)(A + n * 128 + kc + a_k4);
        if (relu) {
            v.x = fmaxf(v.x, 0.f); v.y = fmaxf(v.y, 0.f);
            v.z = fmaxf(v.z, 0.f); v.w = fmaxf(v.w, 0.f);
        }
        As[a_k4 + 0][a_row] = v.x; As[a_k4 + 1][a_row] = v.y;
        As[a_k4 + 2][a_row] = v.z; As[a_k4 + 3][a_row] = v.w;
#pragma unroll
        for (int r = 0; r < 8; r++) {
            int idx = r * 256 + tid;
            int k = idx >> 7, j = idx & 127;
            Bs[k][j] = W[(kc + k) * 128 + j];
        }
        __syncthreads();
#pragma unroll
        for (int k = 0; k < 16; k++) {
            float a[4], b[8];
#pragma unroll
            for (int i = 0; i < 4; i++) a[i] = As[k][ty * 4 + i];
#pragma unroll
            for (int j = 0; j < 8; j++) b[j] = Bs[k][tx * 8 + j];
#pragma unroll
            for (int i = 0; i < 4; i++)
#pragma unroll
                for (int j = 0; j < 8; j++) acc[i][j] = fmaf(a[i], b[j], acc[i][j]);
        }
        __syncthreads();
    }
#pragma unroll
    for (int i = 0; i < 4; i++) {
        int n = nbase + ty * 4 + i;
        if (n >= NN) continue;
#pragma unroll
        for (int j = 0; j < 8; j++) out[n * 128 + tx * 8 + j] = acc[i][j];
    }
}

// agg init: bias + self-loop contribution
__global__ void gcn_init(const float* __restrict__ hW, const float* __restrict__ bvec,
                         const float* __restrict__ dinv, float* __restrict__ agg) {
    int idx = blockIdx.x * blockDim.x + threadIdx.x;
    if (idx >= NN * 128) return;
    int n = idx >> 7, j = idx & 127;
    float di = dinv[n];
    agg[idx] = bvec[j] + hW[idx] * di * di;
}

// edge scatter-add, one warp per edge, float4 per lane
__global__ void gcn_agg(const float* __restrict__ hW, const int* __restrict__ src,
                        const int* __restrict__ dst, const float* __restrict__ dinv,
                        float* __restrict__ agg, int E) {
    int gw = (blockIdx.x * blockDim.x + threadIdx.x) >> 5;
    int lane = threadIdx.x & 31;
    if (gw >= E) return;
    int s = src[gw], d = dst[gw];
    float w = dinv[s] * dinv[d];
    float4 v = ((const float4*)(hW + s * 128))[lane];
    float* p = agg + d * 128 + lane * 4;
    atomicAdd(p + 0, v.x * w);
    atomicAdd(p + 1, v.y * w);
    atomicAdd(p + 2, v.z * w);
    atomicAdd(p + 3, v.w * w);
}

// final projection: warp per node, out[N,12] = relu(A) @ W2[128,12]
__global__ void gcn_gemm12(const float* __restrict__ A, const float* __restrict__ W2,
                           float* __restrict__ out12) {
    int warp = (blockIdx.x * blockDim.x + threadIdx.x) >> 5;
    int lane = threadIdx.x & 31;
    if (warp >= NN) return;
    float acc[12];
#pragma unroll
    for (int j = 0; j < 12; j++) acc[j] = 0.f;
    for (int k = lane; k < 128; k += 32) {
        float a = fmaxf(A[warp * 128 + k], 0.f);
#pragma unroll
        for (int j = 0; j < 12; j++) acc[j] = fmaf(a, W2[k * 12 + j], acc[j]);
    }
#pragma unroll
    for (int j = 0; j < 12; j++) {
        float v = acc[j];
#pragma unroll
        for (int o = 16; o; o >>= 1) v += __shfl_down_sync(0xffffffffu, v, o);
        if (lane == 0) out12[warp * 12 + j] = v;
    }
}

__global__ void gcn_init12(const float* __restrict__ hW12, const float* __restrict__ b2,
                           const float* __restrict__ dinv, float* __restrict__ out) {
    int idx = blockIdx.x * blockDim.x + threadIdx.x;
    if (idx >= NN * 12) return;
    int n = idx / 12, j = idx - n * 12;
    float di = dinv[n];
    out[idx] = b2[j] + hW12[idx] * di * di;
}

__global__ void gcn_agg12(const float* __restrict__ hW12, const int* __restrict__ src,
                          const int* __restrict__ dst, const float* __restrict__ dinv,
                          float* __restrict__ out, int E) {
    int idx = blockIdx.x * blockDim.x + threadIdx.x;
    int e = idx >> 4;
    int j = idx & 15;
    if (e >= E || j >= 12) return;
    int s = src[e], d = dst[e];
    float w = dinv[s] * dinv[d];
    atomicAdd(&out[d * 12 + j], hW12[s * 12 + j] * w);
}

// ---------------- launch ----------------
extern "C" void kernel_launch(void* const* d_in, const int* in_sizes, int n_in,
                              void* d_out, int out_size) {
    const float* x    = (const float*)d_in[0];
    const int*   ei   = (const int*)d_in[1];
    const float* Wih0 = (const float*)d_in[2];
    const float* Whh0 = (const float*)d_in[3];
    const float* bih0 = (const float*)d_in[4];
    const float* bhh0 = (const float*)d_in[5];
    const float* Wih1 = (const float*)d_in[6];
    const float* Whh1 = (const float*)d_in[7];
    const float* bih1 = (const float*)d_in[8];
    const float* bhh1 = (const float*)d_in[9];
    const float* W0   = (const float*)d_in[10];
    const float* b0   = (const float*)d_in[11];
    const float* W1   = (const float*)d_in[12];
    const float* b1   = (const float*)d_in[13];
    const float* W2   = (const float*)d_in[14];
    const float* b2   = (const float*)d_in[15];
    float* out = (float*)d_out;

    int E = in_sizes[1] / 2;
    const int* src = ei;
    const int* dst = ei + E;

    float* S;
    cudaGetSymbolAddress((void**)&S, g_scratch);
    float* h0[2] = { S, S + NH };
    float* c0    = S + 2 * (long long)NH;
    float* h1[2] = { S + 3 * (long long)NH, S + 4 * (long long)NH };
    float* c1    = S + 5 * (long long)NH;
    float* hw    = S + 6 * (long long)NH;
    float* agg   = S + 7 * (long long)NH;
    float* dinv  = S + 8 * (long long)NH;
    float* whh0T  = dinv + 65536;
    float* wcat1T = whh0T + 65536;
    float* bias0  = wcat1T + 131072;
    float* bias1  = bias0 + 1024;

    // zero LSTM state (h0[0], c0, h1[0], c1 live in first 6*NH; zeroing ping buffers is harmless)
    {
        int n6 = 6 * NH;
        zero_k<<<(n6 + 255) / 256, 256>>>(S, n6);
    }
    prep_weights<<<(512 * 128 + 255) / 256, 256>>>(Whh0, Wih1, Whh1, bih0, bhh0, bih1, bhh1,
                                                   whh0T, wcat1T, bias0, bias1);
    deg_init<<<(NN + 255) / 256, 256>>>(dinv);
    deg_count<<<(E + 255) / 256, 256>>>(dst, dinv, E);
    deg_rsqrt<<<(NN + 255) / 256, 256>>>(dinv);

    dim3 lgrid((NN + 127) / 128, 4);
    int p = 0;
    for (int t = 0; t < TT; t++) {
        lstm_step<128, true ><<<lgrid, 256>>>(h0[p], nullptr, whh0T, bias0, x, Wih0, t, c0, h0[1 - p]);
        lstm_step<256, false><<<lgrid, 256>>>(h0[1 - p], h1[p], wcat1T, bias1, nullptr, nullptr, 0, c1, h1[1 - p]);
        p ^= 1;
    }
    float* hfin = h1[p];

    // GCN layer 0
    gcn_gemm<<<(NN + 63) / 64, 256>>>(hfin, W0, hw, 0);
    gcn_init<<<(NN * 128 + 255) / 256, 256>>>(hw, b0, dinv, agg);
    gcn_agg<<<(E + 7) / 8, 256>>>(hw, src, dst, dinv, agg, E);
    // GCN layer 1 (relu on input)
    gcn_gemm<<<(NN + 63) / 64, 256>>>(agg, W1, hw, 1);
    gcn_init<<<(NN * 128 + 255) / 256, 256>>>(hw, b1, dinv, agg);
    gcn_agg<<<(E + 7) / 8, 256>>>(hw, src, dst, dinv, agg, E);
    // GCN layer 2 (relu on input, OUT=12) -> d_out
    gcn_gemm12<<<(NN * 32 + 255) / 256, 256>>>(agg, W2, hw);
    gcn_init12<<<(NN * 12 + 255) / 256, 256>>>(hw, b2, dinv, out);
    gcn_agg12<<<(E * 16 + 255) / 256, 256>>>(hw, src, dst, dinv, out, E);
}

// round 3
// speedup vs baseline: 1.0781x; 1.0781x over previous
#include <cuda_runtime.h>
#include <cuda_bf16.h>
#include <math.h>

#define TT   12
#define NN   50000
#define NH   (NN * 128)
#define MTILES 391          // ceil(50000/128)

// ================= scratch =================
//  c0:NH  c1:NH | bf16 region 4NH floats (8 bufs x NH bf16) | hfin hw agg : 3NH
//  dinv:65536 | B0 hi/lo 65536 | B1 hi/lo 131072 | bias 4096
__device__ float g_scratch[9 * NH + 65536 + 65536 + 131072 + 4096];

// ================= PTX helpers (portable, sm_80+) =================
__device__ __forceinline__ unsigned smem_u32(const void* p) {
    unsigned a;
    asm("{ .reg .u64 t; cvta.to.shared.u64 t, %1; cvt.u32.u64 %0, t; }" : "=r"(a) : "l"(p));
    return a;
}

#define LDSM_X4(r0, r1, r2, r3, a) \
    asm volatile("ldmatrix.sync.aligned.m8n8.x4.shared.b16 {%0,%1,%2,%3}, [%4];" \
        : "=r"(r0), "=r"(r1), "=r"(r2), "=r"(r3) : "r"(a))

#define LDSM_X4T(r0, r1, r2, r3, a) \
    asm volatile("ldmatrix.sync.aligned.m8n8.x4.trans.shared.b16 {%0,%1,%2,%3}, [%4];" \
        : "=r"(r0), "=r"(r1), "=r"(r2), "=r"(r3) : "r"(a))

#define MMA16816(d, a, b) \
    asm volatile("mma.sync.aligned.m16n8k16.row.col.f32.bf16.bf16.f32 " \
        "{%0,%1,%2,%3}, {%4,%5,%6,%7}, {%8,%9}, {%0,%1,%2,%3};" \
        : "+f"((d)[0]), "+f"((d)[1]), "+f"((d)[2]), "+f"((d)[3]) \
        : "r"((a)[0]), "r"((a)[1]), "r"((a)[2]), "r"((a)[3]), "r"((b)[0]), "r"((b)[1]))

__device__ __forceinline__ float sigf(float z) { return __fdividef(1.0f, 1.0f + __expf(-z)); }
__device__ __forceinline__ float tanhf_(float z) { return __fdividef(2.0f, 1.0f + __expf(-2.0f * z)) - 1.0f; }

// ================= prep kernels =================
__global__ void zero_k(float* p, int n) {
    int i = blockIdx.x * blockDim.x + threadIdx.x;
    if (i < n) p[i] = 0.0f;
}

__global__ void prep_bias(const float* __restrict__ bih0, const float* __restrict__ bhh0,
                          const float* __restrict__ bih1, const float* __restrict__ bhh1,
                          float* __restrict__ bias0, float* __restrict__ bias1) {
    int i = blockIdx.x * blockDim.x + threadIdx.x;
    if (i < 512) {
        bias0[i] = bih0[i] + bhh0[i];
        bias1[i] = bih1[i] + bhh1[i];
    }
}

// B staged layout: [y][k][col], col = g*32 + j_local, j = y*32 + j_local.
// hi/lo bf16 split of fp32 weight.
template <int K>
__global__ void prepB(const float* __restrict__ src0, const float* __restrict__ src1,
                      __nv_bfloat16* __restrict__ Bh, __nv_bfloat16* __restrict__ Bl) {
    int idx = blockIdx.x * blockDim.x + threadIdx.x;
    if (idx >= 4 * K * 128) return;
    int y = idx / (K * 128);
    int rem = idx - y * (K * 128);
    int k = rem >> 7;
    int col = rem & 127;
    int g = col >> 5, jl = col & 31;
    int ro = g * 128 + (y * 32 + jl);
    float w = (k < 128) ? src0[ro * 128 + k] : src1[ro * 128 + (k - 128)];
    __nv_bfloat16 hi = __float2bfloat16(w);
    __nv_bfloat16 lo = __float2bfloat16(w - __bfloat162float(hi));
    Bh[idx] = hi;
    Bl[idx] = lo;
}

__global__ void deg_init(float* deg) {
    int i = blockIdx.x * blockDim.x + threadIdx.x;
    if (i < NN) deg[i] = 1.0f;
}
__global__ void deg_count(const int* __restrict__ dst, float* deg, int E) {
    int i = blockIdx.x * blockDim.x + threadIdx.x;
    if (i < E) atomicAdd(&deg[dst[i]], 1.0f);
}
__global__ void deg_rsqrt(float* deg) {
    int i = blockIdx.x * blockDim.x + threadIdx.x;
    if (i < NN) deg[i] = rsqrtf(deg[i]);
}

__global__ void recon_h(const __nv_bfloat16* __restrict__ hh, const __nv_bfloat16* __restrict__ hl,
                        float* __restrict__ out) {
    int i = blockIdx.x * blockDim.x + threadIdx.x;
    if (i < NH) out[i] = __bfloat162float(hh[i]) + __bfloat162float(hl[i]);
}

// ================= fused mma.sync LSTM step =================
// grid (391, 4).  block 256 = 8 warps (4 m-warps x 2 n-warps).
// Block tile: 128 rows x 128 cols (cols = g*32 + jl for this y).
// smem union: loading region (A chunks stride-24, B chunks stride-136) / z stage 128x132 f32.
#define SMEM_BYTES 67584
#define AS_H 0
#define AS_L 6144
#define BS_H 12288
#define BS_L 16640

template <int K, bool HASX>
__global__ __launch_bounds__(256, 1)
void lstm_mma(const __nv_bfloat16* __restrict__ Ah0, const __nv_bfloat16* __restrict__ Al0,
              const __nv_bfloat16* __restrict__ Ah1, const __nv_bfloat16* __restrict__ Al1,
              const __nv_bfloat16* __restrict__ Bh_st, const __nv_bfloat16* __restrict__ Bl_st,
              const float* __restrict__ bias, const float* __restrict__ Wih,
              const float* __restrict__ x, int t,
              float* __restrict__ c,
              __nv_bfloat16* __restrict__ Oh, __nv_bfloat16* __restrict__ Ol) {
    extern __shared__ char smem[];
    unsigned sb = smem_u32(smem);
    int tid = threadIdx.x, lane = tid & 31, wid = tid >> 5;
    int wm = wid & 3, wn = wid >> 2;
    int y = blockIdx.y;
    int nbase = blockIdx.x * 128;

    float acc[2][8][4];
#pragma unroll
    for (int mt = 0; mt < 2; mt++)
#pragma unroll
        for (int nt = 0; nt < 8; nt++)
#pragma unroll
            for (int i = 0; i < 4; i++) acc[mt][nt][i] = 0.f;

    // A staging: thread -> (row, 8-col half)
    int ar = tid >> 1, ahalf = tid & 1;
    int an = nbase + ar;
    bool av = an < NN;
    // B staging: thread -> (k, 8-col seg)
    int bk = tid >> 4, bseg = tid & 15;

    // ldmatrix addresses (constant across ksteps)
    unsigned a_ad[2], b_ad[4];
#pragma unroll
    for (int mt = 0; mt < 2; mt++)
        a_ad[mt] = (unsigned)(((wm * 32 + mt * 16 + (lane & 15)) * 24 + (lane >> 4) * 8) * 2);
    {
        int kk = ((lane >> 3) & 1) * 8 + (lane & 7);
#pragma unroll
        for (int np = 0; np < 4; np++) {
            int nn = wn * 64 + np * 16 + (lane >> 4) * 8;
            b_ad[np] = (unsigned)((kk * 136 + nn) * 2);
        }
    }

    for (int kc = 0; kc < K; kc += 16) {
        const __nv_bfloat16* sAh = Ah0;
        const __nv_bfloat16* sAl = Al0;
        int ko = kc;
        if (K == 256 && kc >= 128) { sAh = Ah1; sAl = Al1; ko = kc - 128; }
        uint4 z4 = make_uint4(0u, 0u, 0u, 0u);
        uint4 va = av ? *(const uint4*)(sAh + (size_t)an * 128 + ko + ahalf * 8) : z4;
        uint4 vl = av ? *(const uint4*)(sAl + (size_t)an * 128 + ko + ahalf * 8) : z4;
        *(uint4*)(smem + AS_H + (ar * 24 + ahalf * 8) * 2) = va;
        *(uint4*)(smem + AS_L + (ar * 24 + ahalf * 8) * 2) = vl;
        size_t bo = ((size_t)(y * K + kc + bk)) * 128 + bseg * 8;
        *(uint4*)(smem + BS_H + (bk * 136 + bseg * 8) * 2) = *(const uint4*)(Bh_st + bo);
        *(uint4*)(smem + BS_L + (bk * 136 + bseg * 8) * 2) = *(const uint4*)(Bl_st + bo);
        __syncthreads();

        unsigned ahf[2][4], alf[2][4], bhf[8][2], blf[8][2];
#pragma unroll
        for (int mt = 0; mt < 2; mt++) {
            LDSM_X4(ahf[mt][0], ahf[mt][1], ahf[mt][2], ahf[mt][3], sb + AS_H + a_ad[mt]);
            LDSM_X4(alf[mt][0], alf[mt][1], alf[mt][2], alf[mt][3], sb + AS_L + a_ad[mt]);
        }
#pragma unroll
        for (int np = 0; np < 4; np++) {
            LDSM_X4T(bhf[np * 2][0], bhf[np * 2][1], bhf[np * 2 + 1][0], bhf[np * 2 + 1][1],
                     sb + BS_H + b_ad[np]);
            LDSM_X4T(blf[np * 2][0], blf[np * 2][1], blf[np * 2 + 1][0], blf[np * 2 + 1][1],
                     sb + BS_L + b_ad[np]);
        }
#pragma unroll
        for (int mt = 0; mt < 2; mt++)
#pragma unroll
            for (int nt = 0; nt < 8; nt++) {
                MMA16816(acc[mt][nt], ahf[mt], bhf[nt]);
                MMA16816(acc[mt][nt], alf[mt], bhf[nt]);
                MMA16816(acc[mt][nt], ahf[mt], blf[nt]);
            }
        __syncthreads();
    }

    // stage z to smem
    float* zs = (float*)smem;
#pragma unroll
    for (int mt = 0; mt < 2; mt++)
#pragma unroll
        for (int nt = 0; nt < 8; nt++) {
            int r0 = wm * 32 + mt * 16 + (lane >> 2);
            int c0 = wn * 64 + nt * 8 + (lane & 3) * 2;
            *(float2*)&zs[r0 * 132 + c0] = make_float2(acc[mt][nt][0], acc[mt][nt][1]);
            *(float2*)&zs[(r0 + 8) * 132 + c0] = make_float2(acc[mt][nt][2], acc[mt][nt][3]);
        }
    __syncthreads();

    // fused gate epilogue
#pragma unroll
    for (int w = 0; w < 16; w++) {
        int item = w * 256 + tid;
        int jl = item & 31, rl = item >> 5;
        int n = nbase + rl;
        if (n >= NN) continue;
        int j = y * 32 + jl;
        float zi = zs[rl * 132 + jl]       + bias[j];
        float zf = zs[rl * 132 + 32 + jl]  + bias[128 + j];
        float zg = zs[rl * 132 + 64 + jl]  + bias[256 + j];
        float zo = zs[rl * 132 + 96 + jl]  + bias[384 + j];
        if (HASX) {
            float x0 = x[((size_t)n * TT + t) * 2 + 0];
            float x1 = x[((size_t)n * TT + t) * 2 + 1];
            zi += x0 * Wih[j * 2]           + x1 * Wih[j * 2 + 1];
            zf += x0 * Wih[(128 + j) * 2]   + x1 * Wih[(128 + j) * 2 + 1];
            zg += x0 * Wih[(256 + j) * 2]   + x1 * Wih[(256 + j) * 2 + 1];
            zo += x0 * Wih[(384 + j) * 2]   + x1 * Wih[(384 + j) * 2 + 1];
        }
        float cn = sigf(zf) * c[(size_t)n * 128 + j] + sigf(zi) * tanhf_(zg);
        c[(size_t)n * 128 + j] = cn;
        float h = sigf(zo) * tanhf_(cn);
        __nv_bfloat16 hh = __float2bfloat16(h);
        Oh[(size_t)n * 128 + j] = hh;
        Ol[(size_t)n * 128 + j] = __float2bfloat16(h - __bfloat162float(hh));
    }
}

// ================= GCN (fp32, passing R1 versions) =================
__global__ __launch_bounds__(256)
void gcn_gemm(const float* __restrict__ A, const float* __restrict__ W,
              float* __restrict__ out, int relu) {
    __shared__ float As[16][68];
    __shared__ float Bs[16][128];
    int tid = threadIdx.x;
    int ty = tid >> 4, tx = tid & 15;
    int nbase = blockIdx.x * 64;
    float acc[4][8];
#pragma unroll
    for (int i = 0; i < 4; i++)
#pragma unroll
        for (int j = 0; j < 8; j++) acc[i][j] = 0.f;
    int a_row = tid >> 2;
    int a_k4 = (tid & 3) * 4;
    for (int kc = 0; kc < 128; kc += 16) {
        int n = nbase + a_row;
        float4 v = make_float4(0.f, 0.f, 0.f, 0.f);
        if (n < NN) v = *(const float4*)(A + (size_t)n * 128 + kc + a_k4);
        if (relu) {
            v.x = fmaxf(v.x, 0.f); v.y = fmaxf(v.y, 0.f);
            v.z = fmaxf(v.z, 0.f); v.w = fmaxf(v.w, 0.f);
        }
        As[a_k4 + 0][a_row] = v.x; As[a_k4 + 1][a_row] = v.y;
        As[a_k4 + 2][a_row] = v.z; As[a_k4 + 3][a_row] = v.w;
#pragma unroll
        for (int r8 = 0; r8 < 8; r8++) {
            int idx = r8 * 256 + tid;
            int k = idx >> 7, j = idx & 127;
            Bs[k][j] = W[(kc + k) * 128 + j];
        }
        __syncthreads();
#pragma unroll
        for (int k = 0; k < 16; k++) {
            float a[4], b[8];
#pragma unroll
            for (int i = 0; i < 4; i++) a[i] = As[k][ty * 4 + i];
#pragma unroll
            for (int j = 0; j < 8; j++) b[j] = Bs[k][tx * 8 + j];
#pragma unroll
            for (int i = 0; i < 4; i++)
#pragma unroll
                for (int j = 0; j < 8; j++) acc[i][j] = fmaf(a[i], b[j], acc[i][j]);
        }
        __syncthreads();
    }
#pragma unroll
    for (int i = 0; i < 4; i++) {
        int n = nbase + ty * 4 + i;
        if (n >= NN) continue;
#pragma unroll
        for (int j = 0; j < 8; j++) out[(size_t)n * 128 + tx * 8 + j] = acc[i][j];
    }
}

__global__ void gcn_init(const float* __restrict__ hW, const float* __restrict__ bvec,
                         const float* __restrict__ dinv, float* __restrict__ agg) {
    int idx = blockIdx.x * blockDim.x + threadIdx.x;
    if (idx >= NN * 128) return;
    int n = idx >> 7, j = idx & 127;
    float di = dinv[n];
    agg[idx] = bvec[j] + hW[idx] * di * di;
}

__global__ void gcn_agg(const float* __restrict__ hW, const int* __restrict__ src,
                        const int* __restrict__ dst, const float* __restrict__ dinv,
                        float* __restrict__ agg, int E) {
    int gw = (blockIdx.x * blockDim.x + threadIdx.x) >> 5;
    int lane = threadIdx.x & 31;
    if (gw >= E) return;
    int s = src[gw], d = dst[gw];
    float w = dinv[s] * dinv[d];
    float4 v = ((const float4*)(hW + (size_t)s * 128))[lane];
    float* p = agg + (size_t)d * 128 + lane * 4;
    atomicAdd(p + 0, v.x * w);
    atomicAdd(p + 1, v.y * w);
    atomicAdd(p + 2, v.z * w);
    atomicAdd(p + 3, v.w * w);
}

__global__ void gcn_gemm12(const float* __restrict__ A, const float* __restrict__ W2,
                           float* __restrict__ out12) {
    int warp = (blockIdx.x * blockDim.x + threadIdx.x) >> 5;
    int lane = threadIdx.x & 31;
    if (warp >= NN) return;
    float acc[12];
#pragma unroll
    for (int j = 0; j < 12; j++) acc[j] = 0.f;
    for (int k = lane; k < 128; k += 32) {
        float a = fmaxf(A[(size_t)warp * 128 + k], 0.f);
#pragma unroll
        for (int j = 0; j < 12; j++) acc[j] = fmaf(a, W2[k * 12 + j], acc[j]);
    }
#pragma unroll
    for (int j = 0; j < 12; j++) {
        float v = acc[j];
#pragma unroll
        for (int o = 16; o; o >>= 1) v += __shfl_down_sync(0xffffffffu, v, o);
        if (lane == 0) out12[(size_t)warp * 12 + j] = v;
    }
}

__global__ void gcn_init12(const float* __restrict__ hW12, const float* __restrict__ b2,
                           const float* __restrict__ dinv, float* __restrict__ out) {
    int idx = blockIdx.x * blockDim.x + threadIdx.x;
    if (idx >= NN * 12) return;
    int n = idx / 12, j = idx - n * 12;
    float di = dinv[n];
    out[idx] = b2[j] + hW12[idx] * di * di;
}

__global__ void gcn_agg12(const float* __restrict__ hW12, const int* __restrict__ src,
                          const int* __restrict__ dst, const float* __restrict__ dinv,
                          float* __restrict__ out, int E) {
    int idx = blockIdx.x * blockDim.x + threadIdx.x;
    int e = idx >> 4;
    int j = idx & 15;
    if (e >= E || j >= 12) return;
    int s = src[e], d = dst[e];
    float w = dinv[s] * dinv[d];
    atomicAdd(&out[(size_t)d * 12 + j], hW12[(size_t)s * 12 + j] * w);
}

// ================= launch =================
extern "C" void kernel_launch(void* const* d_in, const int* in_sizes, int n_in,
                              void* d_out, int out_size) {
    const float* x    = (const float*)d_in[0];
    const int*   ei   = (const int*)d_in[1];
    const float* Wih0 = (const float*)d_in[2];
    const float* Whh0 = (const float*)d_in[3];
    const float* bih0 = (const float*)d_in[4];
    const float* bhh0 = (const float*)d_in[5];
    const float* Wih1 = (const float*)d_in[6];
    const float* Whh1 = (const float*)d_in[7];
    const float* bih1 = (const float*)d_in[8];
    const float* bhh1 = (const float*)d_in[9];
    const float* W0   = (const float*)d_in[10];
    const float* b0   = (const float*)d_in[11];
    const float* W1   = (const float*)d_in[12];
    const float* b1   = (const float*)d_in[13];
    const float* W2   = (const float*)d_in[14];
    const float* b2   = (const float*)d_in[15];
    float* out = (float*)d_out;

    int E = in_sizes[1] / 2;
    const int* src = ei;
    const int* dst = ei + E;

    float* S;
    cudaGetSymbolAddress((void**)&S, g_scratch);
    float* c0 = S;
    float* c1 = S + (size_t)NH;
    __nv_bfloat16* BF = (__nv_bfloat16*)(S + 2 * (size_t)NH);
    __nv_bfloat16* h0h[2] = { BF + 0 * (size_t)NH, BF + 4 * (size_t)NH };
    __nv_bfloat16* h0l[2] = { BF + 1 * (size_t)NH, BF + 5 * (size_t)NH };
    __nv_bfloat16* h1h[2] = { BF + 2 * (size_t)NH, BF + 6 * (size_t)NH };
    __nv_bfloat16* h1l[2] = { BF + 3 * (size_t)NH, BF + 7 * (size_t)NH };
    float* hfin = S + 6 * (size_t)NH;
    float* hw   = S + 7 * (size_t)NH;
    float* agg  = S + 8 * (size_t)NH;
    float* dinv = S + 9 * (size_t)NH;
    __nv_bfloat16* B0h = (__nv_bfloat16*)(dinv + 65536);
    __nv_bfloat16* B0l = B0h + 65536;                 // 4*128*128
    __nv_bfloat16* B1h = (__nv_bfloat16*)(dinv + 65536 + 65536);
    __nv_bfloat16* B1l = B1h + 131072;                // 4*256*128
    float* bias0 = dinv + 65536 + 65536 + 131072;
    float* bias1 = bias0 + 512;

    // zero c0,c1 + ping-0 h buffers
    zero_k<<<(4 * NH + 255) / 256, 256>>>(S, 4 * NH);
    prep_bias<<<2, 256>>>(bih0, bhh0, bih1, bhh1, bias0, bias1);
    prepB<128><<<(4 * 128 * 128 + 255) / 256, 256>>>(Whh0, Whh0, B0h, B0l);
    prepB<256><<<(4 * 256 * 128 + 255) / 256, 256>>>(Wih1, Whh1, B1h, B1l);
    deg_init<<<(NN + 255) / 256, 256>>>(dinv);
    deg_count<<<(E + 255) / 256, 256>>>(dst, dinv, E);
    deg_rsqrt<<<(NN + 255) / 256, 256>>>(dinv);

    cudaFuncSetAttribute(lstm_mma<128, true>,  cudaFuncAttributeMaxDynamicSharedMemorySize, SMEM_BYTES);
    cudaFuncSetAttribute(lstm_mma<256, false>, cudaFuncAttributeMaxDynamicSharedMemorySize, SMEM_BYTES);

    dim3 lgrid(MTILES, 4);
    int p = 0;
    for (int t = 0; t < TT; t++) {
        lstm_mma<128, true><<<lgrid, 256, SMEM_BYTES>>>(
            h0h[p], h0l[p], (const __nv_bfloat16*)nullptr, (const __nv_bfloat16*)nullptr,
            B0h, B0l, bias0, Wih0, x, t, c0, h0h[1 - p], h0l[1 - p]);
        lstm_mma<256, false><<<lgrid, 256, SMEM_BYTES>>>(
            h0h[1 - p], h0l[1 - p], h1h[p], h1l[p],
            B1h, B1l, bias1, (const float*)nullptr, (const float*)nullptr, 0,
            c1, h1h[1 - p], h1l[1 - p]);
        p ^= 1;
    }
    recon_h<<<(NH + 255) / 256, 256>>>(h1h[p], h1l[p], hfin);

    gcn_gemm<<<(NN + 63) / 64, 256>>>(hfin, W0, hw, 0);
    gcn_init<<<(NN * 128 + 255) / 256, 256>>>(hw, b0, dinv, agg);
    gcn_agg<<<(E + 7) / 8, 256>>>(hw, src, dst, dinv, agg, E);
    gcn_gemm<<<(NN + 63) / 64, 256>>>(agg, W1, hw, 1);
    gcn_init<<<(NN * 128 + 255) / 256, 256>>>(hw, b1, dinv, agg);
    gcn_agg<<<(E + 7) / 8, 256>>>(hw, src, dst, dinv, agg, E);
    gcn_gemm12<<<(NN * 32 + 255) / 256, 256>>>(agg, W2, hw);
    gcn_init12<<<(NN * 12 + 255) / 256, 256>>>(hw, b2, dinv, out);
    gcn_agg12<<<((size_t)E * 16 + 255) / 256, 256>>>(hw, src, dst, dinv, out, E);
}

// round 5
// speedup vs baseline: 1.4447x; 1.3400x over previous
#include <cuda_runtime.h>
#include <cuda_bf16.h>
#include <math.h>

#define TT   12
#define NN   50000
#define NH   (NN * 128)
#define MTILES 391          // ceil(50000/128)

// ================= scratch =================
//  c0:NH  c1:NH | bf16 region 4NH floats (8 bufs x NH bf16) | hfin hw agg : 3NH
//  dinv:65536 | B0 hi/lo 65536 | B1 hi/lo 131072 | bias 4096
__device__ float g_scratch[9 * NH + 65536 + 65536 + 131072 + 4096];

// ================= PTX helpers (portable, sm_80+) =================
__device__ __forceinline__ unsigned smem_u32(const void* p) {
    unsigned a;
    asm("{ .reg .u64 t; cvta.to.shared.u64 t, %1; cvt.u32.u64 %0, t; }" : "=r"(a) : "l"(p));
    return a;
}
__device__ __forceinline__ void cp16(unsigned dst, const void* src) {
    asm volatile("cp.async.cg.shared.global [%0], [%1], 16;" :: "r"(dst), "l"(src));
}
#define CP_COMMIT() asm volatile("cp.async.commit_group;" ::: "memory")
#define CP_WAIT0()  asm volatile("cp.async.wait_group 0;" ::: "memory")
#define CP_WAIT1()  asm volatile("cp.async.wait_group 1;" ::: "memory")

#define LDSM_X4(r0, r1, r2, r3, a) \
    asm volatile("ldmatrix.sync.aligned.m8n8.x4.shared.b16 {%0,%1,%2,%3}, [%4];" \
        : "=r"(r0), "=r"(r1), "=r"(r2), "=r"(r3) : "r"(a))

#define LDSM_X4T(r0, r1, r2, r3, a) \
    asm volatile("ldmatrix.sync.aligned.m8n8.x4.trans.shared.b16 {%0,%1,%2,%3}, [%4];" \
        : "=r"(r0), "=r"(r1), "=r"(r2), "=r"(r3) : "r"(a))

#define MMA16816(d, a, b) \
    asm volatile("mma.sync.aligned.m16n8k16.row.col.f32.bf16.bf16.f32 " \
        "{%0,%1,%2,%3}, {%4,%5,%6,%7}, {%8,%9}, {%0,%1,%2,%3};" \
        : "+f"((d)[0]), "+f"((d)[1]), "+f"((d)[2]), "+f"((d)[3]) \
        : "r"((a)[0]), "r"((a)[1]), "r"((a)[2]), "r"((a)[3]), "r"((b)[0]), "r"((b)[1]))

__device__ __forceinline__ float sigf(float z) { return __fdividef(1.0f, 1.0f + __expf(-z)); }
__device__ __forceinline__ float tanhf_(float z) { return __fdividef(2.0f, 1.0f + __expf(-2.0f * z)) - 1.0f; }

// ================= prep kernels =================
__global__ void zero_k(float* p, int n) {
    int i = blockIdx.x * blockDim.x + threadIdx.x;
    if (i < n) p[i] = 0.0f;
}

// merged prep: bias sums + both B stagings.
// B staged layout: [y (8)][k (K)][col (64)], col = g*16 + jl, j = y*16 + jl.
__global__ void prep_all(const float* __restrict__ bih0, const float* __restrict__ bhh0,
                         const float* __restrict__ bih1, const float* __restrict__ bhh1,
                         const float* __restrict__ Whh0,
                         const float* __restrict__ Wih1, const float* __restrict__ Whh1,
                         __nv_bfloat16* __restrict__ B0h, __nv_bfloat16* __restrict__ B0l,
                         __nv_bfloat16* __restrict__ B1h, __nv_bfloat16* __restrict__ B1l,
                         float* __restrict__ bias0, float* __restrict__ bias1) {
    int idx = blockIdx.x * blockDim.x + threadIdx.x;
    if (idx < 512) {
        bias0[idx] = bih0[idx] + bhh0[idx];
        bias1[idx] = bih1[idx] + bhh1[idx];
    }
    if (idx < 8 * 128 * 64) {                 // B0 (K=128)
        int y = idx >> 13;
        int rem = idx & 8191;
        int k = rem >> 6, col = rem & 63;
        int ro = (col >> 4) * 128 + y * 16 + (col & 15);
        float w = Whh0[ro * 128 + k];
        __nv_bfloat16 hi = __float2bfloat16(w);
        B0h[idx] = hi;
        B0l[idx] = __float2bfloat16(w - __bfloat162float(hi));
    }
    if (idx < 8 * 256 * 64) {                 // B1 (K=256)
        int y = idx >> 14;
        int rem = idx & 16383;
        int k = rem >> 6, col = rem & 63;
        int ro = (col >> 4) * 128 + y * 16 + (col & 15);
        float w = (k < 128) ? Wih1[ro * 128 + k] : Whh1[ro * 128 + (k - 128)];
        __nv_bfloat16 hi = __float2bfloat16(w);
        B1h[idx] = hi;
        B1l[idx] = __float2bfloat16(w - __bfloat162float(hi));
    }
}

__global__ void deg_init(float* deg) {
    int i = blockIdx.x * blockDim.x + threadIdx.x;
    if (i < NN) deg[i] = 1.0f;
}
__global__ void deg_count(const int* __restrict__ dst, float* deg, int E) {
    int i = blockIdx.x * blockDim.x + threadIdx.x;
    if (i < E) atomicAdd(&deg[dst[i]], 1.0f);
}
__global__ void deg_rsqrt(float* deg) {
    int i = blockIdx.x * blockDim.x + threadIdx.x;
    if (i < NN) deg[i] = rsqrtf(deg[i]);
}

__global__ void recon_h(const __nv_bfloat16* __restrict__ hh, const __nv_bfloat16* __restrict__ hl,
                        float* __restrict__ out) {
    int i = blockIdx.x * blockDim.x + threadIdx.x;
    if (i < NH) out[i] = __bfloat162float(hh[i]) + __bfloat162float(hl[i]);
}

// ================= persistent mma.sync LSTM step =================
// grid (gx, 8): y-block owns 64 gate-cols (4 gates x 16 j, j = y*16+jl).
// B (K x 64, hi+lo) resident in smem; A streamed via 3-buffer cp.async ring.
// smem: B [0, K*288) ; stage/z region [K*288, K*288+36864)
template <int K, bool HASX>
__global__ __launch_bounds__(256)
void lstm_mma(const __nv_bfloat16* __restrict__ Ah0, const __nv_bfloat16* __restrict__ Al0,
              const __nv_bfloat16* __restrict__ Ah1, const __nv_bfloat16* __restrict__ Al1,
              const __nv_bfloat16* __restrict__ Bh_st, const __nv_bfloat16* __restrict__ Bl_st,
              const float* __restrict__ bias, const float* __restrict__ Wih,
              const float* __restrict__ x, int t,
              float* __restrict__ c,
              __nv_bfloat16* __restrict__ Oh, __nv_bfloat16* __restrict__ Ol) {
    extern __shared__ char smem[];
    unsigned sb = smem_u32(smem);
    const int NK = K / 16;
    const unsigned BSZ = (unsigned)(K * 288);          // B hi (K*144) + B lo (K*144)
    const unsigned STG = sb + BSZ;                     // A ring (3 x 12288) / z (36864)
    int tid = threadIdx.x, lane = tid & 31, wid = tid >> 5;
    int wm = wid & 3, wn = wid >> 2;
    int y = blockIdx.y;

    // ---- B resident load (once) ----
    {
        size_t bbase = (size_t)y * K * 64;
        for (int i = tid; i < K * 8; i += 256) {
            int k = i >> 3, seg = i & 7;
            unsigned d = sb + (unsigned)(k * 144 + seg * 16);
            cp16(d, Bh_st + bbase + (size_t)k * 64 + seg * 8);
            cp16(d + (unsigned)(K * 144), Bl_st + bbase + (size_t)k * 64 + seg * 8);
        }
        CP_COMMIT();
        CP_WAIT0();
    }
    __syncthreads();

    // constant ldmatrix addresses
    unsigned a_ad[2];
#pragma unroll
    for (int mt = 0; mt < 2; mt++)
        a_ad[mt] = (unsigned)(((wm * 32 + mt * 16 + (lane & 15)) * 24 + (lane >> 4) * 8) * 2);
    int bkk = ((lane >> 3) & 1) * 8 + (lane & 7);
    unsigned b_col2 = (unsigned)((wn * 32 + (lane >> 4) * 8) * 2);

    int arow = tid >> 1, ahalf = tid & 1;
    unsigned a_dst = (unsigned)((arow * 24 + ahalf * 8) * 2);
    float* zs = (float*)(smem + BSZ);

    for (int m = blockIdx.x; m < MTILES; m += gridDim.x) {
        int nbase = m * 128;
        int srow = nbase + arow;
        if (srow >= NN) srow = NN - 1;
        size_t soff = (size_t)srow * 128 + ahalf * 8;

        // prologue: chunk 0
        {
            const __nv_bfloat16* sH = (K == 256 && 0 >= 8) ? Ah1 : Ah0;
            const __nv_bfloat16* sL = (K == 256 && 0 >= 8) ? Al1 : Al0;
            unsigned d = STG + a_dst;
            cp16(d, sH + soff);
            cp16(d + 6144u, sL + soff);
            CP_COMMIT();
        }

        float acc[2][4][4];
#pragma unroll
        for (int mt = 0; mt < 2; mt++)
#pragma unroll
            for (int nf = 0; nf < 4; nf++)
#pragma unroll
                for (int i = 0; i < 4; i++) acc[mt][nf][i] = 0.f;

        for (int kc = 0; kc < NK; kc++) {
            if (kc + 1 < NK) {
                int kn = kc + 1;
                const __nv_bfloat16* sH = (K == 256 && kn >= 8) ? Ah1 : Ah0;
                const __nv_bfloat16* sL = (K == 256 && kn >= 8) ? Al1 : Al0;
                int ko = (K == 256 && kn >= 8) ? (kn * 16 - 128) : kn * 16;
                unsigned d = STG + (unsigned)((kn % 3) * 12288) + a_dst;
                cp16(d, sH + soff + ko);
                cp16(d + 6144u, sL + soff + ko);
                CP_COMMIT();
                CP_WAIT1();
            } else {
                CP_WAIT0();
            }
            __syncthreads();

            unsigned abuf = STG + (unsigned)((kc % 3) * 12288);
            unsigned ah[2][4], al[2][4], bh[4][2], bl[4][2];
#pragma unroll
            for (int mt = 0; mt < 2; mt++) {
                LDSM_X4(ah[mt][0], ah[mt][1], ah[mt][2], ah[mt][3], abuf + a_ad[mt]);
                LDSM_X4(al[mt][0], al[mt][1], al[mt][2], al[mt][3], abuf + 6144u + a_ad[mt]);
            }
            unsigned bad = sb + (unsigned)(((kc * 16 + bkk) * 72) * 2) + b_col2;
#pragma unroll
            for (int np = 0; np < 2; np++) {
                LDSM_X4T(bh[np * 2][0], bh[np * 2][1], bh[np * 2 + 1][0], bh[np * 2 + 1][1],
                         bad + np * 32u);
                LDSM_X4T(bl[np * 2][0], bl[np * 2][1], bl[np * 2 + 1][0], bl[np * 2 + 1][1],
                         bad + (unsigned)(K * 144) + np * 32u);
            }
#pragma unroll
            for (int mt = 0; mt < 2; mt++)
#pragma unroll
                for (int nf = 0; nf < 4; nf++) {
                    MMA16816(acc[mt][nf], ah[mt], bh[nf]);
                    MMA16816(acc[mt][nf], al[mt], bh[nf]);
                    MMA16816(acc[mt][nf], ah[mt], bl[nf]);
                }
        }

        __syncthreads();         // A-ring reads done -> reuse region as z
#pragma unroll
        for (int mt = 0; mt < 2; mt++)
#pragma unroll
            for (int nf = 0; nf < 4; nf++) {
                int r0 = wm * 32 + mt * 16 + (lane >> 2);
                int c0 = wn * 32 + nf * 8 + (lane & 3) * 2;
                *(float2*)&zs[r0 * 72 + c0] = make_float2(acc[mt][nf][0], acc[mt][nf][1]);
                *(float2*)&zs[(r0 + 8) * 72 + c0] = make_float2(acc[mt][nf][2], acc[mt][nf][3]);
            }
        __syncthreads();

        // fused gate epilogue: 8 items/thread, 16 j's per block
#pragma unroll
        for (int it = 0; it < 8; it++) {
            int item = it * 256 + tid;
            int jl = item & 15, rl = item >> 4;
            int n = nbase + rl;
            if (n >= NN) continue;
            int j = y * 16 + jl;
            float zi = zs[rl * 72 + jl]      + bias[j];
            float zf = zs[rl * 72 + 16 + jl] + bias[128 + j];
            float zg = zs[rl * 72 + 32 + jl] + bias[256 + j];
            float zo = zs[rl * 72 + 48 + jl] + bias[384 + j];
            if (HASX) {
                float x0 = x[((size_t)n * TT + t) * 2 + 0];
                float x1 = x[((size_t)n * TT + t) * 2 + 1];
                zi += x0 * Wih[j * 2]         + x1 * Wih[j * 2 + 1];
                zf += x0 * Wih[(128 + j) * 2] + x1 * Wih[(128 + j) * 2 + 1];
                zg += x0 * Wih[(256 + j) * 2] + x1 * Wih[(256 + j) * 2 + 1];
                zo += x0 * Wih[(384 + j) * 2] + x1 * Wih[(384 + j) * 2 + 1];
            }
            float cn = sigf(zf) * c[(size_t)n * 128 + j] + sigf(zi) * tanhf_(zg);
            c[(size_t)n * 128 + j] = cn;
            float h = sigf(zo) * tanhf_(cn);
            __nv_bfloat16 hh = __float2bfloat16(h);
            Oh[(size_t)n * 128 + j] = hh;
            Ol[(size_t)n * 128 + j] = __float2bfloat16(h - __bfloat162float(hh));
        }
        __syncthreads();         // z region free before next m's chunk0
    }
}

// ================= GCN (fp32) =================
__global__ __launch_bounds__(256)
void gcn_gemm(const float* __restrict__ A, const float* __restrict__ W,
              float* __restrict__ out, int relu) {
    __shared__ float As[16][68];
    __shared__ float Bs[16][128];
    int tid = threadIdx.x;
    int ty = tid >> 4, tx = tid & 15;
    int nbase = blockIdx.x * 64;
    float acc[4][8];
#pragma unroll
    for (int i = 0; i < 4; i++)
#pragma unroll
        for (int j = 0; j < 8; j++) acc[i][j] = 0.f;
    int a_row = tid >> 2;
    int a_k4 = (tid & 3) * 4;
    for (int kc = 0; kc < 128; kc += 16) {
        int n = nbase + a_row;
        float4 v = make_float4(0.f, 0.f, 0.f, 0.f);
        if (n < NN) v = *(const float4*)(A + (size_t)n * 128 + kc + a_k4);
        if (relu) {
            v.x = fmaxf(v.x, 0.f); v.y = fmaxf(v.y, 0.f);
            v.z = fmaxf(v.z, 0.f); v.w = fmaxf(v.w, 0.f);
        }
        As[a_k4 + 0][a_row] = v.x; As[a_k4 + 1][a_row] = v.y;
        As[a_k4 + 2][a_row] = v.z; As[a_k4 + 3][a_row] = v.w;
#pragma unroll
        for (int r8 = 0; r8 < 8; r8++) {
            int idx = r8 * 256 + tid;
            int k = idx >> 7, j = idx & 127;
            Bs[k][j] = W[(kc + k) * 128 + j];
        }
        __syncthreads();
#pragma unroll
        for (int k = 0; k < 16; k++) {
            float a[4], b[8];
#pragma unroll
            for (int i = 0; i < 4; i++) a[i] = As[k][ty * 4 + i];
#pragma unroll
            for (int j = 0; j < 8; j++) b[j] = Bs[k][tx * 8 + j];
#pragma unroll
            for (int i = 0; i < 4; i++)
#pragma unroll
                for (int j = 0; j < 8; j++) acc[i][j] = fmaf(a[i], b[j], acc[i][j]);
        }
        __syncthreads();
    }
#pragma unroll
    for (int i = 0; i < 4; i++) {
        int n = nbase + ty * 4 + i;
        if (n >= NN) continue;
#pragma unroll
        for (int j = 0; j < 8; j++) out[(size_t)n * 128 + tx * 8 + j] = acc[i][j];
    }
}

__global__ void gcn_init(const float* __restrict__ hW, const float* __restrict__ bvec,
                         const float* __restrict__ dinv, float* __restrict__ agg) {
    int idx = blockIdx.x * blockDim.x + threadIdx.x;
    if (idx >= NN * 128) return;
    int n = idx >> 7, j = idx & 127;
    float di = dinv[n];
    agg[idx] = bvec[j] + hW[idx] * di * di;
}

__global__ void gcn_agg(const float* __restrict__ hW, const int* __restrict__ src,
                        const int* __restrict__ dst, const float* __restrict__ dinv,
                        float* __restrict__ agg, int E) {
    int gw = (blockIdx.x * blockDim.x + threadIdx.x) >> 5;
    int lane = threadIdx.x & 31;
    if (gw >= E) return;
    int s = src[gw], d = dst[gw];
    float w = dinv[s] * dinv[d];
    float4 v = ((const float4*)(hW + (size_t)s * 128))[lane];
    float* p = agg + (size_t)d * 128 + lane * 4;
    atomicAdd(p + 0, v.x * w);
    atomicAdd(p + 1, v.y * w);
    atomicAdd(p + 2, v.z * w);
    atomicAdd(p + 3, v.w * w);
}

__global__ void gcn_gemm12(const float* __restrict__ A, const float* __restrict__ W2,
                           float* __restrict__ out12) {
    int warp = (blockIdx.x * blockDim.x + threadIdx.x) >> 5;
    int lane = threadIdx.x & 31;
    if (warp >= NN) return;
    float acc[12];
#pragma unroll
    for (int j = 0; j < 12; j++) acc[j] = 0.f;
    for (int k = lane; k < 128; k += 32) {
        float a = fmaxf(A[(size_t)warp * 128 + k], 0.f);
#pragma unroll
        for (int j = 0; j < 12; j++) acc[j] = fmaf(a, W2[k * 12 + j], acc[j]);
    }
#pragma unroll
    for (int j = 0; j < 12; j++) {
        float v = acc[j];
#pragma unroll
        for (int o = 16; o; o >>= 1) v += __shfl_down_sync(0xffffffffu, v, o);
        if (lane == 0) out12[(size_t)warp * 12 + j] = v;
    }
}

__global__ void gcn_init12(const float* __restrict__ hW12, const float* __restrict__ b2,
                           const float* __restrict__ dinv, float* __restrict__ out) {
    int idx = blockIdx.x * blockDim.x + threadIdx.x;
    if (idx >= NN * 12) return;
    int n = idx / 12, j = idx - n * 12;
    float di = dinv[n];
    out[idx] = b2[j] + hW12[idx] * di * di;
}

__global__ void gcn_agg12(const float* __restrict__ hW12, const int* __restrict__ src,
                          const int* __restrict__ dst, const float* __restrict__ dinv,
                          float* __restrict__ out, int E) {
    int idx = blockIdx.x * blockDim.x + threadIdx.x;
    int e = idx >> 4;
    int j = idx & 15;
    if (e >= E || j >= 12) return;
    int s = src[e], d = dst[e];
    float w = dinv[s] * dinv[d];
    atomicAdd(&out[(size_t)d * 12 + j], hW12[(size_t)s * 12 + j] * w);
}

// ================= launch =================
extern "C" void kernel_launch(void* const* d_in, const int* in_sizes, int n_in,
                              void* d_out, int out_size) {
    const float* x    = (const float*)d_in[0];
    const int*   ei   = (const int*)d_in[1];
    const float* Wih0 = (const float*)d_in[2];
    const float* Whh0 = (const float*)d_in[3];
    const float* bih0 = (const float*)d_in[4];
    const float* bhh0 = (const float*)d_in[5];
    const float* Wih1 = (const float*)d_in[6];
    const float* Whh1 = (const float*)d_in[7];
    const float* bih1 = (const float*)d_in[8];
    const float* bhh1 = (const float*)d_in[9];
    const float* W0   = (const float*)d_in[10];
    const float* b0   = (const float*)d_in[11];
    const float* W1   = (const float*)d_in[12];
    const float* b1   = (const float*)d_in[13];
    const float* W2   = (const float*)d_in[14];
    const float* b2   = (const float*)d_in[15];
    float* out = (float*)d_out;

    int E = in_sizes[1] / 2;
    const int* src = ei;
    const int* dst = ei + E;

    float* S;
    cudaGetSymbolAddress((void**)&S, g_scratch);
    float* c0 = S;
    float* c1 = S + (size_t)NH;
    __nv_bfloat16* BF = (__nv_bfloat16*)(S + 2 * (size_t)NH);
    __nv_bfloat16* h0h[2] = { BF + 0 * (size_t)NH, BF + 4 * (size_t)NH };
    __nv_bfloat16* h0l[2] = { BF + 1 * (size_t)NH, BF + 5 * (size_t)NH };
    __nv_bfloat16* h1h[2] = { BF + 2 * (size_t)NH, BF + 6 * (size_t)NH };
    __nv_bfloat16* h1l[2] = { BF + 3 * (size_t)NH, BF + 7 * (size_t)NH };
    float* hfin = S + 6 * (size_t)NH;
    float* hw   = S + 7 * (size_t)NH;
    float* agg  = S + 8 * (size_t)NH;
    float* dinv = S + 9 * (size_t)NH;
    __nv_bfloat16* B0h = (__nv_bfloat16*)(dinv + 65536);
    __nv_bfloat16* B0l = B0h + 65536;
    __nv_bfloat16* B1h = (__nv_bfloat16*)(dinv + 65536 + 65536);
    __nv_bfloat16* B1l = B1h + 131072;
    float* bias0 = dinv + 65536 + 65536 + 131072;
    float* bias1 = bias0 + 512;

    // launch #0..#4 are prep; #5 is the first lstm_mma (ncu -s 5 -c 1 target)
    zero_k<<<(4 * NH + 255) / 256, 256>>>(S, 4 * NH);
    prep_all<<<512, 256>>>(bih0, bhh0, bih1, bhh1, Whh0, Wih1, Whh1,
                           B0h, B0l, B1h, B1l, bias0, bias1);
    deg_init<<<(NN + 255) / 256, 256>>>(dinv);
    deg_count<<<(E + 255) / 256, 256>>>(dst, dinv, E);
    deg_rsqrt<<<(NN + 255) / 256, 256>>>(dinv);

    const int SM0 = 128 * 288 + 36864;   // 73728
    const int SM1 = 256 * 288 + 36864;   // 110592
    cudaFuncSetAttribute(lstm_mma<128, true>,  cudaFuncAttributeMaxDynamicSharedMemorySize, SM0);
    cudaFuncSetAttribute(lstm_mma<256, false>, cudaFuncAttributeMaxDynamicSharedMemorySize, SM1);

    dim3 g0(38, 8), g1(19, 8);
    int p = 0;
    for (int t = 0; t < TT; t++) {
        lstm_mma<128, true><<<g0, 256, SM0>>>(
            h0h[p], h0l[p], (const __nv_bfloat16*)nullptr, (const __nv_bfloat16*)nullptr,
            B0h, B0l, bias0, Wih0, x, t, c0, h0h[1 - p], h0l[1 - p]);
        lstm_mma<256, false><<<g1, 256, SM1>>>(
            h0h[1 - p], h0l[1 - p], h1h[p], h1l[p],
            B1h, B1l, bias1, (const float*)nullptr, (const float*)nullptr, 0,
            c1, h1h[1 - p], h1l[1 - p]);
        p ^= 1;
    }
    recon_h<<<(NH + 255) / 256, 256>>>(h1h[p], h1l[p], hfin);

    gcn_gemm<<<(NN + 63) / 64, 256>>>(hfin, W0, hw, 0);
    gcn_init<<<(NN * 128 + 255) / 256, 256>>>(hw, b0, dinv, agg);
    gcn_agg<<<(E + 7) / 8, 256>>>(hw, src, dst, dinv, agg, E);
    gcn_gemm<<<(NN + 63) / 64, 256>>>(agg, W1, hw, 1);
    gcn_init<<<(NN * 128 + 255) / 256, 256>>>(hw, b1, dinv, agg);
    gcn_agg<<<(E + 7) / 8, 256>>>(hw, src, dst, dinv, agg, E);
    gcn_gemm12<<<(NN * 32 + 255) / 256, 256>>>(agg, W2, hw);
    gcn_init12<<<(NN * 12 + 255) / 256, 256>>>(hw, b2, dinv, out);
    gcn_agg12<<<((size_t)E * 16 + 255) / 256, 256>>>(hw, src, dst, dinv, out, E);
}